// round 13
// baseline (speedup 1.0000x reference)
#include <cuda_runtime.h>
#include <cuda_fp16.h>
#include <cstdint>

#define NMAX 100000
#define EMAX 1000000

// ---------------- scratch ----------------
__device__ int    g_deg[NMAX];
__device__ int    g_rowptr[NMAX + 1];
__device__ int    g_cursor[NMAX];
__device__ float  g_invdeg[NMAX];
__device__ int    g_bsums[256];
__device__ int    g_eidx[EMAX];
__device__ unsigned long long g_cnt[4];   // global-barrier arrive counters (monotonic)
__device__ unsigned long long g_flag[4];  // global-barrier release epochs (monotonic)
__device__ __half g_xh[(size_t)NMAX * 64];   // x (fp16)
__device__ __half g_xsh[(size_t)NMAX * 64];  // x @ Ws1 (fp16)
__device__ __half g_xnh[(size_t)NMAX * 64];  // x @ Wn1 (fp16)
__device__ __half g_hh[(size_t)NMAX * 64];   // h (fp16)
__device__ __half g_hnh[(size_t)NMAX * 32];  // h @ Wn2 (fp16)

// ---------------- PTX helpers (all <= sm_80 era, no 'a' gate) ----------------
__device__ __forceinline__ void mma_f16(float c[4], uint32_t a0, uint32_t a1,
                                        uint32_t a2, uint32_t a3,
                                        uint32_t b0, uint32_t b1) {
    asm volatile(
        "mma.sync.aligned.m16n8k16.row.col.f32.f16.f16.f32 "
        "{%0,%1,%2,%3}, {%4,%5,%6,%7}, {%8,%9}, {%0,%1,%2,%3};"
        : "+f"(c[0]), "+f"(c[1]), "+f"(c[2]), "+f"(c[3])
        : "r"(a0), "r"(a1), "r"(a2), "r"(a3), "r"(b0), "r"(b1));
}
__device__ __forceinline__ void ldsm4(uint32_t& r0, uint32_t& r1, uint32_t& r2,
                                      uint32_t& r3, uint32_t addr) {
    asm volatile("ldmatrix.sync.aligned.m8n8.x4.shared.b16 {%0,%1,%2,%3}, [%4];"
        : "=r"(r0), "=r"(r1), "=r"(r2), "=r"(r3) : "r"(addr));
}
__device__ __forceinline__ void cp16(uint32_t saddr, const void* g) {
    asm volatile("cp.async.ca.shared.global [%0], [%1], 16;" :: "r"(saddr), "l"(g));
}
#define CP_COMMIT() asm volatile("cp.async.commit_group;" ::: "memory")

// ---------------- prep: x -> fp16 ----------------
__global__ void k_prep(const float* __restrict__ x, int n) {
    int i = blockIdx.x * blockDim.x + threadIdx.x;
    if (i < n * 32) {
        float2 v = ((const float2*)x)[i];
        ((__half2*)g_xh)[i] = __float22half2_rn(v);
    }
}

// ---------------- fused CSR build (zero -> count -> scan -> scatter) ----------------
// grid MUST be 148 blocks x 256 thr (one per SM; co-resident even beside hgemm1).
// Global barriers: monotonic epoch counters, deterministic across graph replays.
__device__ __forceinline__ void gbar(int k, unsigned long long baseval, int nb) {
    __syncthreads();
    if (threadIdx.x == 0) {
        __threadfence();
        unsigned long long old = atomicAdd(&g_cnt[k], 1ULL);
        if ((old + 1) % (unsigned long long)nb == 0ULL) {
            __threadfence();
            atomicAdd(&g_flag[k], 1ULL);
        }
        while (*(volatile unsigned long long*)&g_flag[k] <= baseval) {
            __nanosleep(64);
        }
        __threadfence();
    }
    __syncthreads();
}

__global__ void __launch_bounds__(256) k_csr(
    const int* __restrict__ src, const int* __restrict__ dst, int n, int e)
{
    __shared__ unsigned long long sbase[4];
    __shared__ int ssum[256];
    int tid = threadIdx.x, b = blockIdx.x;
    int nb = gridDim.x;
    int T = nb * 256;
    int gt = b * 256 + tid;

    if (tid < 4) sbase[tid] = *(volatile unsigned long long*)&g_flag[tid];
    __syncthreads();
    unsigned long long b0v = sbase[0], b1v = sbase[1], b2v = sbase[2], b3v = sbase[3];

    // phase 0: zero degrees
    for (int i = gt; i < n; i += T) g_deg[i] = 0;
    gbar(0, b0v, nb);

    // phase 1: count (int4)
    int e4 = e >> 2;
    for (int i = gt; i < e4; i += T) {
        int4 d = ((const int4*)dst)[i];
        atomicAdd(&g_deg[d.x], 1);
        atomicAdd(&g_deg[d.y], 1);
        atomicAdd(&g_deg[d.z], 1);
        atomicAdd(&g_deg[d.w], 1);
    }
    for (int i = e4 * 4 + gt; i < e; i += T) atomicAdd(&g_deg[dst[i]], 1);
    gbar(1, b1v, nb);

    // phase 2a: block-chunk sums + local scan
    int C = (n + nb - 1) / nb;            // elems per block
    int pt = (C + 255) >> 8;              // elems per thread
    int cbase = b * C;
    int cend = cbase + C; if (cend > n) cend = n;
    int mystart = cbase + tid * pt;
    int s = 0;
    for (int j = 0; j < pt; j++) {
        int i = mystart + j;
        if (i < cend) s += g_deg[i];
    }
    ssum[tid] = s;
    __syncthreads();
#pragma unroll
    for (int off = 1; off < 256; off <<= 1) {
        int tv = (tid >= off) ? ssum[tid - off] : 0;
        __syncthreads();
        ssum[tid] += tv;
        __syncthreads();
    }
    int excl = ssum[tid] - s;             // exclusive prefix within block
    if (tid == 0) g_bsums[b] = ssum[255]; // block total
    gbar(2, b2v, nb);

    // phase 2b: prefix over block sums, then write rowptr/cursor/invdeg
    ssum[tid] = (tid < b) ? g_bsums[tid] : 0;
    __syncthreads();
#pragma unroll
    for (int off = 128; off > 0; off >>= 1) {
        if (tid < off) ssum[tid] += ssum[tid + off];
        __syncthreads();
    }
    int run = ssum[0] + excl;
    for (int j = 0; j < pt; j++) {
        int i = mystart + j;
        if (i < cend) {
            g_rowptr[i] = run;
            g_cursor[i] = run;
            int d = g_deg[i];
            g_invdeg[i] = 1.0f / (float)(d > 1 ? d : 1);
            run += d;
        }
    }
    if (b == 0 && tid == 0) g_rowptr[n] = e;
    gbar(3, b3v, nb);

    // phase 3: scatter (int4)
    for (int i = gt; i < e4; i += T) {
        int4 d = ((const int4*)dst)[i];
        int4 sv = ((const int4*)src)[i];
        g_eidx[atomicAdd(&g_cursor[d.x], 1)] = sv.x;
        g_eidx[atomicAdd(&g_cursor[d.y], 1)] = sv.y;
        g_eidx[atomicAdd(&g_cursor[d.z], 1)] = sv.z;
        g_eidx[atomicAdd(&g_cursor[d.w], 1)] = sv.w;
    }
    for (int i = e4 * 4 + gt; i < e; i += T)
        g_eidx[atomicAdd(&g_cursor[dst[i]], 1)] = src[i];
}

// ---------------- layer-1 GEMM: [xs|xn] = x @ [Ws1|Wn1], staged epilogue ----------
#define LHP 72
static constexpr int HG1_B = 128 * LHP * 2;                 // 18432 B
static constexpr int HG1_SMEM = HG1_B + 2 * 128 * LHP * 2;  // 55296 B

__global__ void __launch_bounds__(256, 2) k_hgemm1(
    const float* __restrict__ ws, const float* __restrict__ wn, int n, int ntiles)
{
    extern __shared__ char smraw[];
    __half* Bs = (__half*)smraw;                  // [128][LHP]
    __half* As = (__half*)(smraw + HG1_B);        // [2][128][LHP]
    int tid = threadIdx.x, wid = tid >> 5, lane = tid & 31;

    if (blockIdx.x >= (unsigned)ntiles) return;

    for (int idx = tid; idx < 4096; idx += 256) {
        int k = idx >> 6, nn = idx & 63;
        Bs[nn * LHP + k]        = __float2half_rn(ws[idx]);
        Bs[(64 + nn) * LHP + k] = __float2half_rn(wn[idx]);
    }

    {
        int base = blockIdx.x * 128;
        for (int c = tid; c < 1024; c += 256) {
            int r = c >> 3, q = c & 7;
            int node = base + r; if (node >= n) node = n - 1;
            uint32_t sa = (uint32_t)__cvta_generic_to_shared(As + r * LHP + q * 8);
            cp16(sa, g_xh + (size_t)node * 64 + q * 8);
        }
        CP_COMMIT();
    }

    int wm = wid & 3, wq = wid >> 2;
    int g = lane >> 2, t = lane & 3;
    int rowoff = (lane & 7) + ((lane >> 3) & 1) * 8;
    int koff = (lane >> 4) * 8;

    uint32_t As_u32 = (uint32_t)__cvta_generic_to_shared(As);
    uint32_t Bs_u32 = (uint32_t)__cvta_generic_to_shared(Bs);
    uint32_t aoff[2], boff[4];
#pragma unroll
    for (int m = 0; m < 2; m++)
        aoff[m] = (uint32_t)(((wm * 32 + m * 16 + rowoff) * LHP + koff) * 2);
#pragma unroll
    for (int p = 0; p < 4; p++)
        boff[p] = Bs_u32 + (uint32_t)(((wq * 64 + p * 16 + rowoff) * LHP + koff) * 2);

    int buf = 0;
    for (int tile = blockIdx.x; tile < ntiles; tile += gridDim.x, buf ^= 1) {
        int nxt = tile + gridDim.x;
        if (nxt < ntiles) {
            int base = nxt * 128;
            __half* dst = As + (buf ^ 1) * 128 * LHP;
            for (int c = tid; c < 1024; c += 256) {
                int r = c >> 3, q = c & 7;
                int node = base + r; if (node >= n) node = n - 1;
                uint32_t sa = (uint32_t)__cvta_generic_to_shared(dst + r * LHP + q * 8);
                cp16(sa, g_xh + (size_t)node * 64 + q * 8);
            }
            CP_COMMIT();
            asm volatile("cp.async.wait_group 1;" ::: "memory");
        } else {
            asm volatile("cp.async.wait_group 0;" ::: "memory");
        }
        __syncthreads();

        uint32_t Ab = As_u32 + (uint32_t)(buf * 128 * LHP * 2);
        float acc[2][8][4];
#pragma unroll
        for (int m = 0; m < 2; m++)
#pragma unroll
            for (int nt = 0; nt < 8; nt++)
#pragma unroll
                for (int i = 0; i < 4; i++) acc[m][nt][i] = 0.f;

#pragma unroll
        for (int ks = 0; ks < 4; ks++) {
            uint32_t kb = ks * 32;
            uint32_t a[2][4];
            ldsm4(a[0][0], a[0][1], a[0][2], a[0][3], Ab + aoff[0] + kb);
            ldsm4(a[1][0], a[1][1], a[1][2], a[1][3], Ab + aoff[1] + kb);
#pragma unroll
            for (int p = 0; p < 4; p++) {
                uint32_t q0, q1, q2, q3;
                ldsm4(q0, q1, q2, q3, boff[p] + kb);
                mma_f16(acc[0][2 * p],     a[0][0], a[0][1], a[0][2], a[0][3], q0, q2);
                mma_f16(acc[0][2 * p + 1], a[0][0], a[0][1], a[0][2], a[0][3], q1, q3);
                mma_f16(acc[1][2 * p],     a[1][0], a[1][1], a[1][2], a[1][3], q0, q2);
                mma_f16(acc[1][2 * p + 1], a[1][0], a[1][1], a[1][2], a[1][3], q1, q3);
            }
        }

        // ---- staged epilogue ----
        __syncthreads();
        __half* S = As + buf * 128 * LHP;
        int n0 = tile * 128;
        if (wq == 0) {
#pragma unroll
            for (int m = 0; m < 2; m++) {
                int lr = wm * 32 + m * 16 + g;
#pragma unroll
                for (int nt = 0; nt < 8; nt++) {
                    int col = nt * 8 + 2 * t;
                    *(__half2*)&S[lr * LHP + col] =
                        __floats2half2_rn(acc[m][nt][0], acc[m][nt][1]);
                    *(__half2*)&S[(lr + 8) * LHP + col] =
                        __floats2half2_rn(acc[m][nt][2], acc[m][nt][3]);
                }
            }
        }
        __syncthreads();
        for (int c2 = tid; c2 < 1024; c2 += 256) {
            int r = c2 >> 3, q = c2 & 7;
            int node = n0 + r;
            if (node < n)
                *(uint4*)((char*)(g_xsh + (size_t)node * 64) + q * 16) =
                    *(const uint4*)((const char*)S + r * 144 + q * 16);
        }
        __syncthreads();
        if (wq == 1) {
#pragma unroll
            for (int m = 0; m < 2; m++) {
                int lr = wm * 32 + m * 16 + g;
#pragma unroll
                for (int nt = 0; nt < 8; nt++) {
                    int col = nt * 8 + 2 * t;
                    *(__half2*)&S[lr * LHP + col] =
                        __floats2half2_rn(acc[m][nt][0], acc[m][nt][1]);
                    *(__half2*)&S[(lr + 8) * LHP + col] =
                        __floats2half2_rn(acc[m][nt][2], acc[m][nt][3]);
                }
            }
        }
        __syncthreads();
        for (int c2 = tid; c2 < 1024; c2 += 256) {
            int r = c2 >> 3, q = c2 & 7;
            int node = n0 + r;
            if (node < n)
                *(uint4*)((char*)(g_xnh + (size_t)node * 64) + q * 16) =
                    *(const uint4*)((const char*)S + r * 144 + q * 16);
        }
        __syncthreads();
    }
}

// ---------------- layer-1 aggregation: h = relu(xs + b1 + invdeg * sum(xn[src])) ----
__global__ void k_agg1(const float* __restrict__ bias, int n) {
    int warp = (blockIdx.x * blockDim.x + threadIdx.x) >> 5;
    int lane = threadIdx.x & 31;
    if (warp >= n) return;
    int start = g_rowptr[warp], end = g_rowptr[warp + 1];
    const __half2* xn2 = (const __half2*)g_xnh;
    float ax = 0.f, ay = 0.f;
    int e = start;
    for (; e + 8 <= end; e += 8) {
        float2 v[8];
#pragma unroll
        for (int j = 0; j < 8; j++)
            v[j] = __half22float2(xn2[(size_t)g_eidx[e + j] * 32 + lane]);
#pragma unroll
        for (int j = 0; j < 8; j++) { ax += v[j].x; ay += v[j].y; }
    }
    for (; e < end; e++) {
        float2 a = __half22float2(xn2[(size_t)g_eidx[e] * 32 + lane]);
        ax += a.x; ay += a.y;
    }
    float id = g_invdeg[warp];
    float2 xs = __half22float2(((const __half2*)g_xsh)[(size_t)warp * 32 + lane]);
    float b0 = __ldg(&bias[2 * lane]);
    float b1 = __ldg(&bias[2 * lane + 1]);
    float hx = fmaxf(xs.x + b0 + ax * id, 0.f);
    float hy = fmaxf(xs.y + b1 + ay * id, 0.f);
    ((__half2*)g_hh)[(size_t)warp * 32 + lane] = __floats2half2_rn(hx, hy);
}

// ---------------- layer-2 GEMM: [out|hn] = h @ [Ws2|Wn2], staged epilogue ----------
__global__ void __launch_bounds__(256, 2) k_hgemm2(
    const float* __restrict__ ws, const float* __restrict__ wn,
    const float* __restrict__ bias, float* __restrict__ out, int n, int ntiles)
{
    __shared__ __half Bs[64 * LHP];
    __shared__ __half As[2][128 * LHP];
    int tid = threadIdx.x, wid = tid >> 5, lane = tid & 31;

    if (blockIdx.x >= (unsigned)ntiles) return;

    for (int idx = tid; idx < 2048; idx += 256) {
        int k = idx >> 5, nn = idx & 31;
        Bs[nn * LHP + k]        = __float2half_rn(ws[idx]);
        Bs[(32 + nn) * LHP + k] = __float2half_rn(wn[idx]);
    }

    {
        int base = blockIdx.x * 128;
        for (int c = tid; c < 1024; c += 256) {
            int r = c >> 3, q = c & 7;
            int node = base + r; if (node >= n) node = n - 1;
            uint32_t sa = (uint32_t)__cvta_generic_to_shared(&As[0][r * LHP + q * 8]);
            cp16(sa, g_hh + (size_t)node * 64 + q * 8);
        }
        CP_COMMIT();
    }

    int wm = wid & 3, wq = wid >> 2;
    int g = lane >> 2, t = lane & 3;
    int rowoff = (lane & 7) + ((lane >> 3) & 1) * 8;
    int koff = (lane >> 4) * 8;

    uint32_t As_u32 = (uint32_t)__cvta_generic_to_shared(&As[0][0]);
    uint32_t Bs_u32 = (uint32_t)__cvta_generic_to_shared(&Bs[0]);
    uint32_t aoff[2], boff[2];
#pragma unroll
    for (int m = 0; m < 2; m++)
        aoff[m] = (uint32_t)(((wm * 32 + m * 16 + rowoff) * LHP + koff) * 2);
#pragma unroll
    for (int p = 0; p < 2; p++)
        boff[p] = Bs_u32 + (uint32_t)(((wq * 32 + p * 16 + rowoff) * LHP + koff) * 2);

    int buf = 0;
    for (int tile = blockIdx.x; tile < ntiles; tile += gridDim.x, buf ^= 1) {
        int nxt = tile + gridDim.x;
        if (nxt < ntiles) {
            int base = nxt * 128;
            for (int c = tid; c < 1024; c += 256) {
                int r = c >> 3, q = c & 7;
                int node = base + r; if (node >= n) node = n - 1;
                uint32_t sa = (uint32_t)__cvta_generic_to_shared(&As[buf ^ 1][r * LHP + q * 8]);
                cp16(sa, g_hh + (size_t)node * 64 + q * 8);
            }
            CP_COMMIT();
            asm volatile("cp.async.wait_group 1;" ::: "memory");
        } else {
            asm volatile("cp.async.wait_group 0;" ::: "memory");
        }
        __syncthreads();

        uint32_t Ab = As_u32 + (uint32_t)(buf * 128 * LHP * 2);
        float acc[2][4][4];
#pragma unroll
        for (int m = 0; m < 2; m++)
#pragma unroll
            for (int nt = 0; nt < 4; nt++)
#pragma unroll
                for (int i = 0; i < 4; i++) acc[m][nt][i] = 0.f;

#pragma unroll
        for (int ks = 0; ks < 4; ks++) {
            uint32_t kb = ks * 32;
            uint32_t a[2][4];
            ldsm4(a[0][0], a[0][1], a[0][2], a[0][3], Ab + aoff[0] + kb);
            ldsm4(a[1][0], a[1][1], a[1][2], a[1][3], Ab + aoff[1] + kb);
#pragma unroll
            for (int p = 0; p < 2; p++) {
                uint32_t q0, q1, q2, q3;
                ldsm4(q0, q1, q2, q3, boff[p] + kb);
                mma_f16(acc[0][2 * p],     a[0][0], a[0][1], a[0][2], a[0][3], q0, q2);
                mma_f16(acc[0][2 * p + 1], a[0][0], a[0][1], a[0][2], a[0][3], q1, q3);
                mma_f16(acc[1][2 * p],     a[1][0], a[1][1], a[1][2], a[1][3], q0, q2);
                mma_f16(acc[1][2 * p + 1], a[1][0], a[1][1], a[1][2], a[1][3], q1, q3);
            }
        }

        // ---- staged epilogue ----
        __syncthreads();
        char* Sb = (char*)&As[buf][0];
        int n0 = tile * 128;
        float* F = (float*)Sb;
        if (wq == 0) {
#pragma unroll
            for (int m = 0; m < 2; m++) {
                int lr = wm * 32 + m * 16 + g;
#pragma unroll
                for (int nt = 0; nt < 4; nt++) {
                    int col = nt * 8 + 2 * t;
                    float b0 = __ldg(&bias[col]);
                    float b1 = __ldg(&bias[col + 1]);
                    *(float2*)&F[lr * 36 + col] =
                        make_float2(acc[m][nt][0] + b0, acc[m][nt][1] + b1);
                    *(float2*)&F[(lr + 8) * 36 + col] =
                        make_float2(acc[m][nt][2] + b0, acc[m][nt][3] + b1);
                }
            }
        }
        __syncthreads();
        for (int c2 = tid; c2 < 1024; c2 += 256) {
            int r = c2 >> 3, q = c2 & 7;
            int node = n0 + r;
            if (node < n)
                *(uint4*)((char*)(out + (size_t)node * 32) + q * 16) =
                    *(const uint4*)(Sb + r * 144 + q * 16);
        }
        __syncthreads();
        __half* H = (__half*)Sb;
        if (wq == 1) {
#pragma unroll
            for (int m = 0; m < 2; m++) {
                int lr = wm * 32 + m * 16 + g;
#pragma unroll
                for (int nt = 0; nt < 4; nt++) {
                    int col = nt * 8 + 2 * t;
                    *(__half2*)&H[lr * LHP + col] =
                        __floats2half2_rn(acc[m][nt][0], acc[m][nt][1]);
                    *(__half2*)&H[(lr + 8) * LHP + col] =
                        __floats2half2_rn(acc[m][nt][2], acc[m][nt][3]);
                }
            }
        }
        __syncthreads();
        for (int c2 = tid; c2 < 512; c2 += 256) {
            int r = c2 >> 2, q = c2 & 3;
            int node = n0 + r;
            if (node < n)
                *(uint4*)((char*)(g_hnh + (size_t)node * 32) + q * 16) =
                    *(const uint4*)(Sb + r * 144 + q * 16);
        }
        __syncthreads();
    }
}

// ---------------- layer-2 aggregation: out += invdeg * sum(hn[src]) ----------------
__global__ void k_agg2(float* __restrict__ out, int n) {
    int warp = (blockIdx.x * blockDim.x + threadIdx.x) >> 5;
    int lane = threadIdx.x & 31;
    if (warp >= n) return;
    int start = g_rowptr[warp], end = g_rowptr[warp + 1];
    float acc = 0.f;
    int e = start;
    for (; e + 8 <= end; e += 8) {
        float v[8];
#pragma unroll
        for (int j = 0; j < 8; j++)
            v[j] = __half2float(g_hnh[(size_t)g_eidx[e + j] * 32 + lane]);
#pragma unroll
        for (int j = 0; j < 8; j++) acc += v[j];
    }
    for (; e < end; e++)
        acc += __half2float(g_hnh[(size_t)g_eidx[e] * 32 + lane]);
    out[(size_t)warp * 32 + lane] += acc * g_invdeg[warp];
}

// ---------------- launcher (6 launches, fork/join) ----------------
extern "C" void kernel_launch(void* const* d_in, const int* in_sizes, int n_in,
                              void* d_out, int out_size) {
    const float* x   = (const float*)d_in[0];
    const int*   src = (const int*)d_in[1];
    const int*   dst = (const int*)d_in[2];
    const float* ws1 = (const float*)d_in[3];
    const float* wn1 = (const float*)d_in[4];
    const float* b1  = (const float*)d_in[5];
    const float* ws2 = (const float*)d_in[6];
    const float* wn2 = (const float*)d_in[7];
    const float* b2  = (const float*)d_in[8];
    float* out = (float*)d_out;

    int N = in_sizes[0] / 64;
    int E = in_sizes[1];
    int ntiles = (N + 127) >> 7;
    int pgrid = 296;

    static cudaStream_t s2 = nullptr;
    static cudaEvent_t evFork = nullptr, evJoin = nullptr;
    if (!s2) {
        cudaStreamCreateWithFlags(&s2, cudaStreamNonBlocking);
        cudaEventCreateWithFlags(&evFork, cudaEventDisableTiming);
        cudaEventCreateWithFlags(&evJoin, cudaEventDisableTiming);
        cudaFuncSetAttribute(k_hgemm1, cudaFuncAttributeMaxDynamicSharedMemorySize, HG1_SMEM);
    }

    cudaEventRecord(evFork, 0);
    cudaStreamWaitEvent(s2, evFork, 0);

    k_prep<<<(N * 32 + 255) / 256, 256>>>(x, N);                 // 1 (s0)
    k_csr<<<148, 256, 0, s2>>>(src, dst, N, E);                  // 2 (s2: whole CSR build)
    k_hgemm1<<<pgrid, 256, HG1_SMEM>>>(ws1, wn1, N, ntiles);     // 3 (s0)
    cudaEventRecord(evJoin, s2);
    cudaStreamWaitEvent(0, evJoin, 0);

    k_agg1<<<(N + 7) / 8, 256>>>(b1, N);                         // 4 (s0, profiled)
    k_hgemm2<<<pgrid, 256>>>(ws2, wn2, b2, out, N, ntiles);      // 5 (s0)
    k_agg2<<<(N + 7) / 8, 256>>>(out, N);                        // 6 (s0)
}